// round 5
// baseline (speedup 1.0000x reference)
#include <cuda_runtime.h>
#include <cuda_bf16.h>
#include <mma.h>

using namespace nvcuda;

#define NUM_C 2048
#define LEN_Q 32
#define D 640
#define GK_PAD 72          // 64 + 8 bf16 pad
#define AS_BYTES (2 * 64 * GK_PAD * 2)   // 18432 per operand (2 stages)

// Scratch (no cudaMalloc allowed)
__device__ __nv_bfloat16 g_u_bf[NUM_C * D];
__device__ __nv_bfloat16 g_w_bf[D * D];
__device__ __nv_bfloat16 g_yg[NUM_C * D];

// grid barrier state (self-restoring: sense flips 1 then 0 each launch)
__device__ unsigned g_count = 0;
__device__ unsigned g_sense = 0;

__device__ __forceinline__ void cp_async16(void* smem_dst, const void* gmem_src) {
    unsigned s = (unsigned)__cvta_generic_to_shared(smem_dst);
    asm volatile("cp.async.ca.shared.global [%0], [%1], 16;\n" :: "r"(s), "l"(gmem_src));
}

__device__ __forceinline__ void grid_barrier(unsigned target_sense) {
    __syncthreads();
    if (threadIdx.x == 0) {
        __threadfence();
        const unsigned old = atomicAdd(&g_count, 1);
        if (old == gridDim.x - 1) {
            atomicExch(&g_count, 0);     // reset count BEFORE releasing
            __threadfence();
            atomicExch(&g_sense, target_sense);
        } else {
            while (atomicAdd(&g_sense, 0) != target_sense) __nanosleep(32);
        }
        __threadfence();
    }
    __syncthreads();
}

// ---------------------------------------------------------------------------
// One persistent kernel, one wave (4 blocks/SM), three phases:
//  A: W fp32->bf16 (400 tasks) + u = s_b*v_b + k_b in bf16 (256 tasks, 8 batch)
//  B: bf16 wmma GEMM 64x64 tiles, cp.async double-buffered (320 tasks)
//     yg = (W u + b_fc) * gamma1  -> bf16
//  C: LayerNorm(q + yg) * ln_w + ln_b  (8192 tasks of 8 rows, warp-per-row)
// ---------------------------------------------------------------------------
__global__ void __launch_bounds__(256, 4)
k_fused(const float* __restrict__ q, const float* __restrict__ kin,
        const float* __restrict__ v, const float* __restrict__ W,
        const float* __restrict__ bfc, const float* __restrict__ gam,
        const float* __restrict__ lnw, const float* __restrict__ lnb,
        float* __restrict__ out)
{
    __shared__ __align__(16) unsigned char smem_u[2 * AS_BYTES];  // 36864 B
    const int tid  = threadIdx.x;
    const int bid  = blockIdx.x;
    const int grid = gridDim.x;

    // ================= Phase A =================
    for (int t = bid; t < 656; t += grid) {
        if (t < 400) {
            const int i4 = t * 256 + tid;
            const float4 w4 = ((const float4*)W)[i4];
            __nv_bfloat162 p0 = __floats2bfloat162_rn(w4.x, w4.y);
            __nv_bfloat162 p1 = __floats2bfloat162_rn(w4.z, w4.w);
            uint2 pk; pk.x = *(unsigned*)&p0; pk.y = *(unsigned*)&p1;
            ((uint2*)g_w_bf)[i4] = pk;
        } else {
            const int b    = (t - 400) * 8 + (tid >> 5);
            const int lane = tid & 31;
            const float4* vp = (const float4*)(v + b * D);
            const float4* kp = (const float4*)(kin + b * D);
            float4 vv[5], kv[5];
            float s = 0.f;
            #pragma unroll
            for (int j = 0; j < 5; j++) {
                vv[j] = vp[lane + j * 32];
                kv[j] = kp[lane + j * 32];
                s += vv[j].x + vv[j].y + vv[j].z + vv[j].w;
            }
            #pragma unroll
            for (int off = 16; off > 0; off >>= 1) s += __shfl_xor_sync(~0u, s, off);
            uint2* up = (uint2*)(g_u_bf + b * D);
            #pragma unroll
            for (int j = 0; j < 5; j++) {
                __nv_bfloat162 p0 = __floats2bfloat162_rn(fmaf(s, vv[j].x, kv[j].x),
                                                          fmaf(s, vv[j].y, kv[j].y));
                __nv_bfloat162 p1 = __floats2bfloat162_rn(fmaf(s, vv[j].z, kv[j].z),
                                                          fmaf(s, vv[j].w, kv[j].w));
                uint2 pk; pk.x = *(unsigned*)&p0; pk.y = *(unsigned*)&p1;
                up[lane + j * 32] = pk;
            }
        }
    }
    grid_barrier(1);

    // ================= Phase B =================
    {
        __nv_bfloat16* As = (__nv_bfloat16*)smem_u;
        __nv_bfloat16* Bs = (__nv_bfloat16*)(smem_u + AS_BYTES);
        float* Sout = (float*)smem_u;    // aliases As (dead at epilogue)

        const int w  = tid >> 5;
        const int wm = (w >> 1) * 16;    // 4 warps along M
        const int wn = (w & 1) * 32;     // 2 warps along N

        for (int t = bid; t < 320; t += grid) {
            const int bm = (t / 10) * 64;
            const int bn = (t % 10) * 64;

            wmma::fragment<wmma::accumulator, 16, 16, 16, float> acc[2];
            wmma::fill_fragment(acc[0], 0.f);
            wmma::fill_fragment(acc[1], 0.f);

            auto prefetch = [&](int st, int k0) {
                #pragma unroll
                for (int i = 0; i < 2; i++) {
                    const int e = tid + i * 256;        // 0..511
                    const int r = e >> 3;
                    const int c = (e & 7) * 8;
                    cp_async16(&As[st * 64 * GK_PAD + r * GK_PAD + c],
                               &g_u_bf[(bm + r) * D + k0 + c]);
                    cp_async16(&Bs[st * 64 * GK_PAD + r * GK_PAD + c],
                               &g_w_bf[(bn + r) * D + k0 + c]);
                }
                asm volatile("cp.async.commit_group;\n");
            };

            prefetch(0, 0);
            #pragma unroll 1
            for (int kt = 0; kt < 10; kt++) {
                if (kt + 1 < 10) {
                    prefetch((kt + 1) & 1, (kt + 1) * 64);
                    asm volatile("cp.async.wait_group 1;\n");
                } else {
                    asm volatile("cp.async.wait_group 0;\n");
                }
                __syncthreads();
                const int st = kt & 1;
                #pragma unroll
                for (int kc = 0; kc < 4; kc++) {
                    wmma::fragment<wmma::matrix_a, 16, 16, 16, __nv_bfloat16, wmma::row_major> a;
                    wmma::fragment<wmma::matrix_b, 16, 16, 16, __nv_bfloat16, wmma::col_major> bb[2];
                    wmma::load_matrix_sync(a, &As[st * 64 * GK_PAD + wm * GK_PAD + kc * 16], GK_PAD);
                    wmma::load_matrix_sync(bb[0], &Bs[st * 64 * GK_PAD + wn * GK_PAD + kc * 16], GK_PAD);
                    wmma::load_matrix_sync(bb[1], &Bs[st * 64 * GK_PAD + (wn + 16) * GK_PAD + kc * 16], GK_PAD);
                    wmma::mma_sync(acc[0], a, bb[0], acc[0]);
                    wmma::mma_sync(acc[1], a, bb[1], acc[1]);
                }
                __syncthreads();
            }

            wmma::store_matrix_sync(&Sout[wm * 64 + wn],      acc[0], 64, wmma::mem_row_major);
            wmma::store_matrix_sync(&Sout[wm * 64 + wn + 16], acc[1], 64, wmma::mem_row_major);
            __syncthreads();

            #pragma unroll
            for (int i = 0; i < 8; i++) {
                const int e   = tid + i * 256;    // 0..2047 (bf162 units)
                const int r   = e >> 5;
                const int cp2 = e & 31;
                const int col = bn + cp2 * 2;
                const float x0 = (Sout[r * 64 + cp2 * 2 + 0] + __ldg(&bfc[col + 0])) * __ldg(&gam[col + 0]);
                const float x1 = (Sout[r * 64 + cp2 * 2 + 1] + __ldg(&bfc[col + 1])) * __ldg(&gam[col + 1]);
                *(__nv_bfloat162*)&g_yg[(bm + r) * D + col] = __floats2bfloat162_rn(x0, x1);
            }
            __syncthreads();
        }
    }
    grid_barrier(0);

    // ================= Phase C =================
    {
        float* s_yg = (float*)smem_u;                 // 2560 B
        float* s_w  = (float*)(smem_u + 2560);        // 2560 B
        float* s_b  = (float*)(smem_u + 5120);        // 2560 B

        for (int i = tid; i < D; i += 256) { s_w[i] = lnw[i]; s_b[i] = lnb[i]; }

        const int w    = tid >> 5;
        const int lane = tid & 31;
        const float inv_d = 1.0f / (float)D;

        for (int t = bid; t < NUM_C * 4; t += grid) {
            const int b       = t >> 2;
            const int rowbase = (t & 3) * 8;

            __syncthreads();   // protect s_yg reuse across tasks
            for (int i = tid; i < D / 2; i += 256) {
                const __nv_bfloat162 p = ((const __nv_bfloat162*)(g_yg + b * D))[i];
                const float2 f = __bfloat1622float2(p);
                s_yg[2 * i + 0] = f.x;
                s_yg[2 * i + 1] = f.y;
            }
            __syncthreads();

            const long row = (long)b * LEN_Q + rowbase + w;
            const float4* qrow = (const float4*)(q + row * D);
            float4* orow       = (float4*)(out + row * D);

            float4 z[5];
            float sum = 0.f, sq = 0.f;
            #pragma unroll
            for (int j = 0; j < 5; j++) {
                const int c4 = j * 32 + lane;
                const float4 qv = __ldcs(&qrow[c4]);
                const float4 yv = *(const float4*)(s_yg + c4 * 4);
                z[j].x = qv.x + yv.x; z[j].y = qv.y + yv.y;
                z[j].z = qv.z + yv.z; z[j].w = qv.w + yv.w;
                sum += z[j].x + z[j].y + z[j].z + z[j].w;
                sq = fmaf(z[j].x, z[j].x, sq); sq = fmaf(z[j].y, z[j].y, sq);
                sq = fmaf(z[j].z, z[j].z, sq); sq = fmaf(z[j].w, z[j].w, sq);
            }
            #pragma unroll
            for (int off = 16; off > 0; off >>= 1) {
                sum += __shfl_xor_sync(~0u, sum, off);
                sq  += __shfl_xor_sync(~0u, sq,  off);
            }
            const float mean = sum * inv_d;
            const float var  = sq * inv_d - mean * mean;
            const float rstd = rsqrtf(var + 1e-5f);

            #pragma unroll
            for (int j = 0; j < 5; j++) {
                const int c4 = j * 32 + lane;
                const int c  = c4 * 4;
                float4 o;
                o.x = (z[j].x - mean) * rstd * s_w[c + 0] + s_b[c + 0];
                o.y = (z[j].y - mean) * rstd * s_w[c + 1] + s_b[c + 1];
                o.z = (z[j].z - mean) * rstd * s_w[c + 2] + s_b[c + 2];
                o.w = (z[j].w - mean) * rstd * s_w[c + 3] + s_b[c + 3];
                __stcs(&orow[c4], o);
            }
        }
    }
}

// ---------------------------------------------------------------------------
// Inputs: 0=q 1=k 2=v 3=w_fc 4=b_fc 5=gamma1 6=ln_w 7=ln_b
// ---------------------------------------------------------------------------
extern "C" void kernel_launch(void* const* d_in, const int* in_sizes, int n_in,
                              void* d_out, int out_size) {
    const float* q     = (const float*)d_in[0];
    const float* k     = (const float*)d_in[1];
    const float* v     = (const float*)d_in[2];
    const float* w_fc  = (const float*)d_in[3];
    const float* b_fc  = (const float*)d_in[4];
    const float* gam   = (const float*)d_in[5];
    const float* ln_w  = (const float*)d_in[6];
    const float* ln_b  = (const float*)d_in[7];
    float* out = (float*)d_out;

    int dev = 0, nsm = 148;
    cudaGetDevice(&dev);
    cudaDeviceGetAttribute(&nsm, cudaDevAttrMultiProcessorCount, dev);

    k_fused<<<nsm * 4, 256>>>(q, k, v, w_fc, b_fc, gam, ln_w, ln_b, out);
}